// round 2
// baseline (speedup 1.0000x reference)
#include <cuda_runtime.h>

#define BB 64
#define TT 2048
#define DK 128
#define DV 128

// ---- packed f32x2 helpers (SASS FFMA2 path — PTX-only) ----
__device__ __forceinline__ unsigned long long pk2(float lo, float hi) {
    unsigned long long r;
    asm("mov.b64 %0, {%1,%2};" : "=l"(r) : "f"(lo), "f"(hi));
    return r;
}
__device__ __forceinline__ unsigned long long fma2(unsigned long long a, unsigned long long b, unsigned long long c) {
    unsigned long long d;
    asm("fma.rn.f32x2 %0, %1, %2, %3;" : "=l"(d) : "l"(a), "l"(b), "l"(c));
    return d;
}
__device__ __forceinline__ unsigned long long mul2_(unsigned long long a, unsigned long long b) {
    unsigned long long d;
    asm("mul.rn.f32x2 %0, %1, %2;" : "=l"(d) : "l"(a), "l"(b));
    return d;
}
__device__ __forceinline__ float2 up2(unsigned long long a) {
    float2 f;
    asm("mov.b64 {%0,%1}, %2;" : "=f"(f.x), "=f"(f.y) : "l"(a));
    return f;
}

struct Buf {
    unsigned long long q2[4];  // 8 q floats (rows krow..krow+8), packed pairwise along k
    unsigned long long k2[4];  // 8 k floats
    float2 v2;                 // 2 v floats for this lane's 2 v columns
};

__global__ void __launch_bounds__(512, 1)
lmm_scan_kernel(const float* __restrict__ q,
                const float* __restrict__ k,
                const float* __restrict__ v,
                const float* __restrict__ alpha,
                const float* __restrict__ rho,
                const float* __restrict__ lam,
                const float* __restrict__ init,
                float* __restrict__ out)
{
    // CTA = (batch, v-half). 16 warps; warp covers k:128 x v:4.
    // Lane = (kg in [0,16), vg in [0,2)): owns k rows [8kg,8kg+8) x v cols {vb+2vg, vb+2vg+1}.
    const int bid   = blockIdx.x;
    const int b     = bid >> 1;
    const int vhalf = bid & 1;
    const int tid   = threadIdx.x;
    const int warp  = tid >> 5;
    const int lane  = tid & 31;
    const int kg    = lane & 15;
    const int vg    = lane >> 4;
    const int vcol  = vhalf * 64 + warp * 4 + vg * 2;   // lane's 2 v columns
    const int krow  = kg * 8;                           // lane's 8 k rows

    // ---- state M[krow..krow+8) x [vcol..vcol+2), packed pairwise along k ----
    unsigned long long M2[4][2];
    {
        const float* ist = init + (size_t)b * DK * DV;
        #pragma unroll
        for (int kp = 0; kp < 4; kp++) {
            const float* r0 = ist + (size_t)(krow + 2 * kp) * DV + vcol;
            const float* r1 = r0 + DV;
            M2[kp][0] = pk2(r0[0], r1[0]);
            M2[kp][1] = pk2(r0[1], r1[1]);
        }
    }

    const size_t bT = (size_t)b * TT;

    auto load = [&](Buf& bf, int t) {
        size_t roff = (bT + (size_t)t) * DK;
        const ulonglong2* qp = reinterpret_cast<const ulonglong2*>(q + roff + krow);
        ulonglong2 x = qp[0], y = qp[1];
        bf.q2[0] = x.x; bf.q2[1] = x.y; bf.q2[2] = y.x; bf.q2[3] = y.y;
        const ulonglong2* kp_ = reinterpret_cast<const ulonglong2*>(k + roff + krow);
        x = kp_[0]; y = kp_[1];
        bf.k2[0] = x.x; bf.k2[1] = x.y; bf.k2[2] = y.x; bf.k2[3] = y.y;
        bf.v2 = *reinterpret_cast<const float2*>(v + roff + vcol);
    };

    auto step = [&](const Buf& bf, float sA, float sR, float sL, int t) {
        float w = sA * sR;
        unsigned long long l2  = pk2(sL, sL);
        float w0 = w * bf.v2.x, w1 = w * bf.v2.y;
        unsigned long long wv0 = pk2(w0, w0);
        unsigned long long wv1 = pk2(w1, w1);
        unsigned long long racc0, racc1;
        #pragma unroll
        for (int kp = 0; kp < 4; kp++) {
            unsigned long long t0 = mul2_(bf.k2[kp], wv0);      // (w*v0)*k
            M2[kp][0] = fma2(l2, M2[kp][0], t0);                // M = l*M + wv*k
            racc0 = (kp == 0) ? mul2_(bf.q2[0], M2[0][0])
                              : fma2(bf.q2[kp], M2[kp][0], racc0);
            unsigned long long t1 = mul2_(bf.k2[kp], wv1);
            M2[kp][1] = fma2(l2, M2[kp][1], t1);
            racc1 = (kp == 0) ? mul2_(bf.q2[0], M2[0][1])
                              : fma2(bf.q2[kp], M2[kp][1], racc1);
        }
        float r0, r1;
        { float2 u = up2(racc0); r0 = u.x + u.y; }
        { float2 u = up2(racc1); r1 = u.x + u.y; }
        // butterfly over the 16 kg groups (lane bits 0..3); vg bit untouched
        #pragma unroll
        for (int m = 1; m <= 8; m <<= 1) {
            r0 += __shfl_xor_sync(0xffffffffu, r0, m);
            r1 += __shfl_xor_sync(0xffffffffu, r1, m);
        }
        if (kg == 0) {
            *reinterpret_cast<float2*>(out + (bT + (size_t)t) * DV + vcol) =
                make_float2(r0, r1);
        }
    };

    // scalars: alpha/rho/lam contiguous over t -> float4 per 4 steps
    float4 sa = *reinterpret_cast<const float4*>(alpha + bT);
    float4 sr = *reinterpret_cast<const float4*>(rho + bT);
    float4 sl = *reinterpret_cast<const float4*>(lam + bT);

    Buf buf0, buf1;
    load(buf0, 0);

    for (int tb = 0; tb < TT; tb += 4) {
        float4 na, nr, nl;

        load(buf1, tb + 1);
        step(buf0, sa.x, sr.x, sl.x, tb + 0);

        load(buf0, tb + 2);
        step(buf1, sa.y, sr.y, sl.y, tb + 1);

        load(buf1, tb + 3);
        {
            int tn = tb + 4; if (tn > TT - 4) tn = TT - 4;
            na = *reinterpret_cast<const float4*>(alpha + bT + tn);
            nr = *reinterpret_cast<const float4*>(rho + bT + tn);
            nl = *reinterpret_cast<const float4*>(lam + bT + tn);
        }
        step(buf0, sa.z, sr.z, sl.z, tb + 2);

        int t4 = tb + 4; if (t4 > TT - 1) t4 = TT - 1;
        load(buf0, t4);
        step(buf1, sa.w, sr.w, sl.w, tb + 3);

        sa = na; sr = nr; sl = nl;
    }
}

extern "C" void kernel_launch(void* const* d_in, const int* in_sizes, int n_in,
                              void* d_out, int out_size)
{
    const float* q     = (const float*)d_in[0];
    const float* k     = (const float*)d_in[1];
    const float* v     = (const float*)d_in[2];
    const float* alpha = (const float*)d_in[3];
    const float* rho   = (const float*)d_in[4];
    const float* lam   = (const float*)d_in[5];
    const float* init  = (const float*)d_in[6];
    float* out = (float*)d_out;
    (void)in_sizes; (void)n_in; (void)out_size;

    lmm_scan_kernel<<<BB * 2, 512>>>(q, k, v, alpha, rho, lam, init, out);
}

// round 3
// speedup vs baseline: 1.2234x; 1.2234x over previous
#include <cuda_runtime.h>

#define BB 64
#define TT 2048
#define DK 128
#define DV 128

// ---- packed f32x2 helpers (SASS FFMA2 path — PTX-only) ----
__device__ __forceinline__ unsigned long long pk2(float lo, float hi) {
    unsigned long long r;
    asm("mov.b64 %0, {%1,%2};" : "=l"(r) : "f"(lo), "f"(hi));
    return r;
}
__device__ __forceinline__ unsigned long long fma2(unsigned long long a, unsigned long long b, unsigned long long c) {
    unsigned long long d;
    asm("fma.rn.f32x2 %0, %1, %2, %3;" : "=l"(d) : "l"(a), "l"(b), "l"(c));
    return d;
}
__device__ __forceinline__ unsigned long long mul2_(unsigned long long a, unsigned long long b) {
    unsigned long long d;
    asm("mul.rn.f32x2 %0, %1, %2;" : "=l"(d) : "l"(a), "l"(b));
    return d;
}
__device__ __forceinline__ float2 up2(unsigned long long a) {
    float2 f;
    asm("mov.b64 {%0,%1}, %2;" : "=f"(f.x), "=f"(f.y) : "l"(a));
    return f;
}

struct Buf {
    unsigned long long q2[4];  // 8 q floats (rows krow..krow+8), packed pairwise along k
    unsigned long long k2[4];  // 8 k floats
    float4 v4;                 // 4 v floats for this lane's 4 v columns
};

__global__ void __launch_bounds__(256, 1)
lmm_scan_kernel(const float* __restrict__ q,
                const float* __restrict__ k,
                const float* __restrict__ v,
                const float* __restrict__ alpha,
                const float* __restrict__ rho,
                const float* __restrict__ lam,
                const float* __restrict__ init,
                float* __restrict__ out)
{
    // CTA = (batch, v-half). 8 warps; warp w covers k rows [16w,16w+16) x 64 v cols.
    // Lane = (kg in {0,1}, vg in [0,16)): owns k [16w+8kg, +8) x v [vbase+4vg, +4).
    // q/k rows are loaded by exactly ONE warp each (no cross-warp duplication).
    const int bid   = blockIdx.x;
    const int b     = bid >> 1;
    const int vhalf = bid & 1;
    const int tid   = threadIdx.x;
    const int warp  = tid >> 5;
    const int lane  = tid & 31;
    const int kg    = lane & 1;
    const int vg    = lane >> 1;
    const int krow  = warp * 16 + kg * 8;       // lane's 8 k rows
    const int vcol  = vhalf * 64 + vg * 4;      // lane's 4 v columns

    // ---- state M[krow..krow+8) x [vcol..vcol+4), packed pairwise along k ----
    unsigned long long M2[4][4];
    {
        const float* ist = init + (size_t)b * DK * DV;
        #pragma unroll
        for (int kp = 0; kp < 4; kp++) {
            const float* r0 = ist + (size_t)(krow + 2 * kp) * DV + vcol;
            const float* r1 = r0 + DV;
            #pragma unroll
            for (int vj = 0; vj < 4; vj++)
                M2[kp][vj] = pk2(r0[vj], r1[vj]);
        }
    }

    const size_t bT = (size_t)b * TT;

    auto load = [&](Buf& bf, int t) {
        size_t roff = (bT + (size_t)t) * DK;
        const ulonglong2* qp = reinterpret_cast<const ulonglong2*>(q + roff + krow);
        ulonglong2 x = qp[0], y = qp[1];
        bf.q2[0] = x.x; bf.q2[1] = x.y; bf.q2[2] = y.x; bf.q2[3] = y.y;
        const ulonglong2* kp_ = reinterpret_cast<const ulonglong2*>(k + roff + krow);
        x = kp_[0]; y = kp_[1];
        bf.k2[0] = x.x; bf.k2[1] = x.y; bf.k2[2] = y.x; bf.k2[3] = y.y;
        bf.v4 = *reinterpret_cast<const float4*>(v + roff + vcol);
    };

    auto step = [&](const Buf& bf, float sA, float sR, float sL, int t) {
        float w = sA * sR;
        unsigned long long l2 = pk2(sL, sL);
        float w0 = w * bf.v4.x, w1 = w * bf.v4.y, w2 = w * bf.v4.z, w3 = w * bf.v4.w;
        unsigned long long wv[4] = { pk2(w0, w0), pk2(w1, w1), pk2(w2, w2), pk2(w3, w3) };
        unsigned long long racc[4];
        #pragma unroll
        for (int kp = 0; kp < 4; kp++) {
            #pragma unroll
            for (int vj = 0; vj < 4; vj++) {
                unsigned long long tt = mul2_(bf.k2[kp], wv[vj]);   // (w*v_j)*k
                M2[kp][vj] = fma2(l2, M2[kp][vj], tt);              // M = l*M + ...
                racc[vj] = (kp == 0) ? mul2_(bf.q2[0], M2[0][vj])   // r += q*M (post-update)
                                     : fma2(bf.q2[kp], M2[kp][vj], racc[vj]);
            }
        }
        float r0, r1, r2s, r3;
        { float2 u = up2(racc[0]); r0  = u.x + u.y; }
        { float2 u = up2(racc[1]); r1  = u.x + u.y; }
        { float2 u = up2(racc[2]); r2s = u.x + u.y; }
        { float2 u = up2(racc[3]); r3  = u.x + u.y; }
        // single butterfly level over the kg bit (lane bit 0)
        r0  += __shfl_xor_sync(0xffffffffu, r0,  1);
        r1  += __shfl_xor_sync(0xffffffffu, r1,  1);
        r2s += __shfl_xor_sync(0xffffffffu, r2s, 1);
        r3  += __shfl_xor_sync(0xffffffffu, r3,  1);
        if (kg == 0) {
            // NOTE: this is a PARTIAL sum over this warp's 16 k rows only —
            // cross-warp accumulation happens via the atomic-free ownership:
            // each warp owns a disjoint k-slice, so partial sums MUST be
            // combined across the 8 warps. We do it with atomicAdd-free
            // reduction: warp w adds into out via atomicAdd? NO — see below:
            // we instead use red.global.add.f32 which is fire-and-forget.
            #pragma unroll
            for (int j = 0; j < 4; j++) {
                float val = (j == 0) ? r0 : (j == 1) ? r1 : (j == 2) ? r2s : r3;
                asm volatile("red.global.add.f32 [%0], %1;"
                             :: "l"(out + (bT + (size_t)t) * DV + vcol + j), "f"(val)
                             : "memory");
            }
        }
    };

    // d_out is poisoned 0xAA — zero this CTA's output region before accumulating.
    // (each CTA owns out[b, :, vhalf*64 .. vhalf*64+64) exclusively)
    for (int idx = tid; idx < TT * 16; idx += 256) {
        int t = idx >> 4;
        int c = (idx & 15) * 4;
        *reinterpret_cast<float4*>(out + (bT + (size_t)t) * DV + vhalf * 64 + c) =
            make_float4(0.f, 0.f, 0.f, 0.f);
    }
    __syncthreads();

    // scalars: alpha/rho/lam contiguous over t -> float4 per 4 steps
    float4 sa = *reinterpret_cast<const float4*>(alpha + bT);
    float4 sr = *reinterpret_cast<const float4*>(rho + bT);
    float4 sl = *reinterpret_cast<const float4*>(lam + bT);

    Buf buf0, buf1, buf2, buf3;
    load(buf0, 0);
    load(buf1, 1);

    for (int tb = 0; tb < TT; tb += 4) {
        float4 na, nr, nl;

        load(buf2, tb + 2);
        step(buf0, sa.x, sr.x, sl.x, tb + 0);

        load(buf3, tb + 3);
        step(buf1, sa.y, sr.y, sl.y, tb + 1);

        {
            int t4 = tb + 4; if (t4 > TT - 1) t4 = TT - 1;
            load(buf0, t4);
            int tn = tb + 4; if (tn > TT - 4) tn = TT - 4;
            na = *reinterpret_cast<const float4*>(alpha + bT + tn);
            nr = *reinterpret_cast<const float4*>(rho + bT + tn);
            nl = *reinterpret_cast<const float4*>(lam + bT + tn);
        }
        step(buf2, sa.z, sr.z, sl.z, tb + 2);

        {
            int t5 = tb + 5; if (t5 > TT - 1) t5 = TT - 1;
            load(buf1, t5);
        }
        step(buf3, sa.w, sr.w, sl.w, tb + 3);

        sa = na; sr = nr; sl = nl;
    }
}

extern "C" void kernel_launch(void* const* d_in, const int* in_sizes, int n_in,
                              void* d_out, int out_size)
{
    const float* q     = (const float*)d_in[0];
    const float* k     = (const float*)d_in[1];
    const float* v     = (const float*)d_in[2];
    const float* alpha = (const float*)d_in[3];
    const float* rho   = (const float*)d_in[4];
    const float* lam   = (const float*)d_in[5];
    const float* init  = (const float*)d_in[6];
    float* out = (float*)d_out;
    (void)in_sizes; (void)n_in; (void)out_size;

    lmm_scan_kernel<<<BB * 2, 256>>>(q, k, v, alpha, rho, lam, init, out);
}